// round 1
// baseline (speedup 1.0000x reference)
#include <cuda_runtime.h>
#include <math.h>

#define B   32
#define EN  256
#define DX  512
#define DZ  256
#define DM  256
#define H   8
#define HD  32
#define LQ  256   // active queries: l in [256,512), l' = l-256

// scratch (device globals; no allocation allowed)
__device__ __align__(16) float g_pe[B*DM];
__device__ __align__(16) float g_Q0[LQ*DM];      // Q0[l'][d] = Qp[256+l']@Wq^T + bq
__device__ __align__(16) float g_P0[B*DM];       // P0[b][d]  = pe[b]@Wq^T
__device__ __align__(16) float g_GQT[H*DM*LQ];   // [h][e][l']
__device__ __align__(16) float g_GPb[B*H*DM];    // [b][h][e]
__device__ __align__(16) float g_SGQ[LQ*H];      // sum over e of GQT
__device__ __align__(16) float g_SGP[B*H];       // sum over e of GPb
__device__ __align__(16) float g_w[B*LQ];        // attention weight on the state key

// ---------------------------------------------------------------- K0a: sinusoidal PE
__global__ void k_pe() {
    int p = blockIdx.x, d = threadIdx.x;
    int i = d >> 1;
    float coef = -(logf(10000.0f) / (float)DM) * (float)(2 * i);
    float dv = expf(coef);
    float arg = (float)p * dv;
    g_pe[p*DM + d] = (d & 1) ? cosf(arg) : sinf(arg);
}

// ---------------------------------------------------------------- K0b: Q0 (rows l>=256 only) and P0
// 288 rows total: rows 0..255 -> Qp[256+r], rows 256..287 -> pe[r-256]
__global__ void k_q0(const float* __restrict__ Qp, const float* __restrict__ Wq,
                     const float* __restrict__ bq) {
    __shared__ float rowS[32][DM];   // 32 rows x 256, 32KB
    int rt = blockIdx.x;             // 0..8 (tiles of 32 rows)
    int dt = blockIdx.y;             // 0..3 (tiles of 64 output dims)
    int tid = threadIdx.x;

    #pragma unroll
    for (int k = 0; k < 32; k++) {
        int lin = k * 256 + tid;
        int r = lin >> 8, c = lin & 255;
        int gi = rt * 32 + r;
        float v = (gi < 256) ? Qp[(256 + gi) * DM + c] : g_pe[(gi - 256) * DM + c];
        rowS[r][c] = v;
    }
    __syncthreads();

    int dl = tid & 63;
    int d = dt * 64 + dl;
    int rbase = (tid >> 6) * 8;
    float bias = (rt < 8) ? bq[d] : 0.0f;
    float acc[8];
    #pragma unroll
    for (int r = 0; r < 8; r++) acc[r] = bias;

    const float4* Wq4 = (const float4*)(Wq + (size_t)d * DM);
    #pragma unroll 8
    for (int c4 = 0; c4 < 64; c4++) {
        float4 w4 = Wq4[c4];
        #pragma unroll
        for (int r = 0; r < 8; r++) {
            float4 r4 = ((const float4*)&rowS[rbase + r][0])[c4];
            acc[r] += r4.x * w4.x + r4.y * w4.y + r4.z * w4.z + r4.w * w4.w;
        }
    }
    #pragma unroll
    for (int r = 0; r < 8; r++) {
        int gi = rt * 32 + rbase + r;
        if (gi < 256) g_Q0[gi * DM + d] = acc[r];
        else          g_P0[(gi - 256) * DM + d] = acc[r];
    }
}

// ---------------------------------------------------------------- K1: GQT[h][e][l'] = sum_d Q0[l'][32h+d] * Wk[32h+d][e]
__global__ void k_gqt(const float* __restrict__ Wk) {
    __shared__ float wks[16][32];    // [ee][d]
    int et = blockIdx.x;             // 0..15 (16 e per tile)
    int h  = blockIdx.y;             // 0..7
    int tid = threadIdx.x;           // l'

    #pragma unroll
    for (int k = 0; k < 2; k++) {
        int lin = k * 256 + tid;     // 0..511
        int ee = lin >> 5, d = lin & 31;
        wks[ee][d] = Wk[(h * 32 + d) * DM + et * 16 + ee];
    }
    __syncthreads();

    float4 q4[8];
    const float4* q0p = (const float4*)(g_Q0 + (size_t)tid * DM + h * 32);
    #pragma unroll
    for (int j = 0; j < 8; j++) q4[j] = q0p[j];

    #pragma unroll
    for (int ee = 0; ee < 16; ee++) {
        float acc = 0.0f;
        const float4* wr = (const float4*)&wks[ee][0];
        #pragma unroll
        for (int j = 0; j < 8; j++) {
            float4 w4 = wr[j];
            acc += q4[j].x * w4.x + q4[j].y * w4.y + q4[j].z * w4.z + q4[j].w * w4.w;
        }
        g_GQT[(h * DM + et * 16 + ee) * LQ + tid] = acc;
    }
}

// ---------------------------------------------------------------- K1b: GPb[b][h][e] = sum_d P0[b][32h+d] * Wk[32h+d][e]
__global__ void k_gpb(const float* __restrict__ Wk) {
    __shared__ float p0s[32];
    int h = blockIdx.x, b = blockIdx.y;
    int e = threadIdx.x;
    if (e < 32) p0s[e] = g_P0[b * DM + h * 32 + e];
    __syncthreads();
    float acc = 0.0f;
    #pragma unroll
    for (int d = 0; d < 32; d++)
        acc += p0s[d] * Wk[(h * 32 + d) * DM + e];
    g_GPb[(b * H + h) * DM + e] = acc;
}

// ---------------------------------------------------------------- K1c: column sums over e
__global__ void k_sums() {
    int tid = threadIdx.x;
    if (blockIdx.x < 8) {
        int h = blockIdx.x;
        float acc = 0.0f;
        for (int e = 0; e < DM; e++) acc += g_GQT[(h * DM + e) * LQ + tid];
        g_SGQ[tid * H + h] = acc;
    } else {
        float acc = 0.0f;
        for (int e = 0; e < DM; e++) acc += g_GPb[tid * DM + e];
        g_SGP[tid] = acc;
    }
}

// ---------------------------------------------------------------- K2: per-(b, l>=256) head deltas -> w
__global__ void k_delta(const float* __restrict__ state, const float* __restrict__ obs) {
    __shared__ float gps[2 * H * DM];  // GPb slices for b0, b1 (16KB)
    __shared__ float red[18 * 256];    // phase-reduction scratch (18KB)
    int lt = blockIdx.x;               // 0..7  (32 l' per tile)
    int bg = blockIdx.y;               // 0..15 (2 b per block)
    int tid = threadIdx.x;
    int b0 = bg * 2;

    #pragma unroll
    for (int k = 0; k < 16; k++)
        gps[k * 256 + tid] = g_GPb[(size_t)b0 * H * DM + k * 256 + tid];
    __syncthreads();

    int lo = tid & 31, p = tid >> 5;
    int lp = lt * 32 + lo;             // l'
    int l = 256 + lp;

    float sdg0[8], sdg1[8];
    #pragma unroll
    for (int h = 0; h < 8; h++) { sdg0[h] = 0.0f; sdg1[h] = 0.0f; }
    float sd0 = 0.0f, sd1 = 0.0f;

    const float* st0 = state + (size_t)b0 * EN * DX;
    const float* st1 = st0 + (size_t)EN * DX;
    const float* ob0 = obs + (size_t)b0 * EN * DZ;
    const float* ob1 = ob0 + (size_t)EN * DZ;

    #pragma unroll 4
    for (int j = 0; j < 32; j++) {
        int e = p * 32 + j;
        float D0 = st0[(size_t)e * DX + l] - ob0[(size_t)e * DZ + lp];
        float D1 = st1[(size_t)e * DX + l] - ob1[(size_t)e * DZ + lp];
        sd0 += D0; sd1 += D1;
        #pragma unroll
        for (int h = 0; h < 8; h++) {
            float g = g_GQT[(h * DM + e) * LQ + lp];
            sdg0[h] = fmaf(D0, g + gps[h * DM + e], sdg0[h]);
            sdg1[h] = fmaf(D1, g + gps[H * DM + h * DM + e], sdg1[h]);
        }
    }

    #pragma unroll
    for (int h = 0; h < 8; h++) {
        red[h * 256 + tid]       = sdg0[h];
        red[(9 + h) * 256 + tid] = sdg1[h];
    }
    red[8 * 256 + tid]  = sd0;
    red[17 * 256 + tid] = sd1;
    __syncthreads();

    if (tid < 64) {
        int bsel = tid >> 5, lo2 = tid & 31;
        int lp2 = lt * 32 + lo2;
        int b = b0 + bsel;
        float sd = 0.0f;
        #pragma unroll
        for (int q = 0; q < 8; q++) sd += red[(bsel * 9 + 8) * 256 + q * 32 + lo2];
        float md = sd * (1.0f / 256.0f);
        float wsum = 0.0f;
        #pragma unroll
        for (int h = 0; h < 8; h++) {
            float sdg = 0.0f;
            #pragma unroll
            for (int q = 0; q < 8; q++) sdg += red[(bsel * 9 + h) * 256 + q * 32 + lo2];
            float sg = g_SGQ[lp2 * H + h] + g_SGP[b * H + h];
            float delta = (sdg - md * sg) * 0.17677669529663688f;   // 1/sqrt(32)
            wsum += 1.0f / (1.0f + expf(-delta));
        }
        g_w[b * LQ + lp2] = wsum * 0.125f;
    }
}

// ---------------------------------------------------------------- K3a: new_state [32,256,512]
__global__ void k_newstate(const float* __restrict__ state, const float* __restrict__ obs,
                           float* __restrict__ out) {
    int idx = blockIdx.x * 256 + threadIdx.x;   // float4 index, 0..1048575
    int l4 = (idx & 127) * 4;
    int be = idx >> 7;
    float4 s4 = ((const float4*)state)[idx];
    float4 o;
    if (l4 < 256) {
        o = s4;
    } else {
        int b = be >> 8;
        int lp4 = (l4 - 256) >> 2;
        float4 o4 = ((const float4*)obs)[be * 64 + lp4];
        float4 w4 = ((const float4*)g_w)[b * 64 + lp4];
        o.x = o4.x + w4.x * (s4.x - o4.x);
        o.y = o4.y + w4.y * (s4.y - o4.y);
        o.z = o4.z + w4.z * (s4.z - o4.z);
        o.w = o4.w + w4.w * (s4.w - o4.w);
    }
    ((float4*)out)[idx] = o;
}

// ---------------------------------------------------------------- K3b: atten [32,512,768] (sparse: 1-2 nonzeros/row)
__global__ void k_atten(float* __restrict__ att) {
    int idx = blockIdx.x * 256 + threadIdx.x;   // float4 index, 0..3145727
    int s4 = (idx % 192) * 4;
    int bl = idx / 192;
    int l = bl & 511;
    int b = bl >> 9;
    float4 v = make_float4(0.0f, 0.0f, 0.0f, 0.0f);
    int d1 = l - s4;
    if ((unsigned)d1 < 4u) {
        float val = (l < 256) ? 1.0f : g_w[b * LQ + (l - 256)];
        if      (d1 == 0) v.x = val;
        else if (d1 == 1) v.y = val;
        else if (d1 == 2) v.z = val;
        else              v.w = val;
    }
    if (l >= 256) {
        int d2 = (l + 256) - s4;
        if ((unsigned)d2 < 4u) {
            float val = 1.0f - g_w[b * LQ + (l - 256)];
            if      (d2 == 0) v.x = val;
            else if (d2 == 1) v.y = val;
            else if (d2 == 2) v.z = val;
            else              v.w = val;
        }
    }
    ((float4*)att)[idx] = v;
}

// ----------------------------------------------------------------
extern "C" void kernel_launch(void* const* d_in, const int* in_sizes, int n_in,
                              void* d_out, int out_size) {
    const float* state = (const float*)d_in[0];
    const float* obs   = (const float*)d_in[1];
    const float* Qp    = (const float*)d_in[2];
    const float* Wq    = (const float*)d_in[3];
    const float* bq    = (const float*)d_in[4];
    const float* Wk    = (const float*)d_in[5];
    // bk (d_in[6]) provably cancels in the masked softmax — unused.
    float* out = (float*)d_out;

    k_pe   <<<32, 256>>>();
    k_q0   <<<dim3(9, 4),  256>>>(Qp, Wq, bq);
    k_gqt  <<<dim3(16, 8), 256>>>(Wk);
    k_gpb  <<<dim3(8, 32), 256>>>(Wk);
    k_sums <<<9, 256>>>();
    k_delta<<<dim3(8, 16), 256>>>(state, obs);

    const int NS = B * EN * DX;       // 4,194,304
    const int AT = B * DX * (DX + DZ);// 12,582,912
    if (out_size >= NS + AT) {
        k_newstate<<<NS / 1024, 256>>>(state, obs, out);
        k_atten   <<<AT / 1024, 256>>>(out + NS);
    } else if (out_size == AT) {
        k_atten   <<<AT / 1024, 256>>>(out);
    } else {
        k_newstate<<<NS / 1024, 256>>>(state, obs, out);
    }
}